// round 6
// baseline (speedup 1.0000x reference)
#include <cuda_runtime.h>
#include <cuda_bf16.h>
#include <math.h>

// ---------------------------------------------------------------------------
// Problem constants
// ---------------------------------------------------------------------------
#define NLEV 16
#define TSZ  (1 << 19)
#define TMASK (TSZ - 1)
#define HASH_PRIME 2654435761u

typedef unsigned long long u64;

// Weight blob: wp1[12*64] | wp2[64*64] | wp3[64] | wt[32*68] | bt[68]
#define OFF_WP1 0
#define OFF_WP2 768
#define OFF_WP3 4864
#define OFF_WT  4928
#define OFF_BT  7104
#define TOTW    7172

struct __align__(16) Weights {
    float wp1[12 * 64];
    float wp2[64 * 64];
    float wp3[64];
    float wt [32 * 68];
    float bt [68];
};
__device__ Weights g_w;

struct LevelP {
    float scale[NLEV];
    int   res[NLEV];
    int   dense[NLEV];
};

// Shared layout (floats), offsets all mult of 4 (16B aligned)
#define SM_ENC   TOTW                 // 2 x 12 x 128 = 3072
#define SM_FEAT  (SM_ENC + 3072)      // 2 x 32 x 128 = 8192
#define SM_H1    (SM_FEAT + 8192)     // 8336 (64x128 + pad; also out-stage 128x65=8320)
#define SM_Z     (SM_H1 + 8336)       // 2 x 128
#define SM_X64   (SM_Z + 256)         // 2 x 128
#define SM_PZ    (SM_X64 + 256)       // 128
#define SMEM_FLOATS (SM_PZ + 128)
#define SMEM_BYTES  (SMEM_FLOATS * 4)

// ---------------------------------------------------------------------------
// f32x2 helpers
// ---------------------------------------------------------------------------
__device__ __forceinline__ u64 dup2(float a) {
    u64 r; asm("mov.b64 %0, {%1, %1};" : "=l"(r) : "f"(a)); return r;
}
__device__ __forceinline__ u64 pack2(float a, float b) {
    u64 r; asm("mov.b64 %0, {%1, %2};" : "=l"(r) : "f"(a), "f"(b)); return r;
}
__device__ __forceinline__ void unpack2(u64 v, float &a, float &b) {
    asm("mov.b64 {%0, %1}, %2;" : "=f"(a), "=f"(b) : "l"(v));
}
__device__ __forceinline__ void fma2(u64 &d, u64 a, u64 b) {
    asm("fma.rn.f32x2 %0, %1, %2, %0;" : "+l"(d) : "l"(a), "l"(b));
}
__device__ __forceinline__ float sigm(float x) {
    return __fdividef(1.0f, 1.0f + __expf(-x));
}
__device__ __forceinline__ void bar_mlp() {
    asm volatile("bar.sync 1, 128;" ::: "memory");
}

// ---------------------------------------------------------------------------
// 8pts x 8cols register-tiled GEMM with A(k+1) prefetch.
//   acc[p*8+c]: points (pg*8+2p, +1), col = (c&3) + cg*4 + (c>>2)*32
//   SWZ: A rows stored with chunk swizzle  chunk' = pg ^ ((k>>2)&3)
// A prefetch reads one row past K (lands in valid adjacent smem; discarded).
// ---------------------------------------------------------------------------
template <int K, int NC, int SWZ, int UNR>
__device__ __forceinline__ void gemm88(u64* __restrict__ acc,
                                       const float* __restrict__ aT,
                                       const float* __restrict__ B,
                                       int pg, int cg) {
    const float* bp = B + cg * 4;
    #define A_PTR(kk) (aT + (kk) * 128 + ((SWZ ? (pg ^ (((kk) >> 2) & 3)) : pg) << 3))
    const float* a0 = A_PTR(0);
    ulonglong2 A0 = *reinterpret_cast<const ulonglong2*>(a0);
    ulonglong2 A1 = *reinterpret_cast<const ulonglong2*>(a0 + 4);
    #pragma unroll UNR
    for (int k = 0; k < K; k++) {
        const float* an = A_PTR(k + 1);
        ulonglong2 nA0 = *reinterpret_cast<const ulonglong2*>(an);
        ulonglong2 nA1 = *reinterpret_cast<const ulonglong2*>(an + 4);
        float4 b0 = *reinterpret_cast<const float4*>(bp + k * NC);
        float4 b1 = *reinterpret_cast<const float4*>(bp + k * NC + 32);
        u64 a[4] = {A0.x, A0.y, A1.x, A1.y};
        float bf[8] = {b0.x, b0.y, b0.z, b0.w, b1.x, b1.y, b1.z, b1.w};
        #pragma unroll
        for (int c = 0; c < 8; c++) {
            u64 bb = dup2(bf[c]);
            fma2(acc[0 * 8 + c], a[0], bb);
            fma2(acc[1 * 8 + c], a[1], bb);
            fma2(acc[2 * 8 + c], a[2], bb);
            fma2(acc[3 * 8 + c], a[3], bb);
        }
        A0 = nA0; A1 = nA1;
    }
    #undef A_PTR
}

// ---------------------------------------------------------------------------
// Prep kernel
// ---------------------------------------------------------------------------
__global__ void prep_weights(const float* __restrict__ W_tiny,
                             const float* __restrict__ b_tiny,
                             const float* __restrict__ Wp1,
                             const float* __restrict__ Wp2,
                             const float* __restrict__ Wp3) {
    int t = threadIdx.x;
    for (int i = t; i < 12 * 64; i += blockDim.x) g_w.wp1[i] = Wp1[i];
    for (int i = t; i < 64 * 64; i += blockDim.x) g_w.wp2[i] = Wp2[i];
    if (t < 64) g_w.wp3[t] = Wp3[t];
    for (int i = t; i < 32 * 68; i += blockDim.x) {
        int k = i / 68, j = i % 68;
        g_w.wt[i] = (j < 65) ? W_tiny[k * 65 + j] : 0.0f;
    }
    if (t < 68) g_w.bt[t] = (t < 65) ? b_tiny[t] : 0.0f;
}

// ---------------------------------------------------------------------------
// Persistent warp-specialized kernel
//   threads 0-127  : gather crew (inputs, sincos encode, hash gather) tile j
//   threads 128-255: MLP crew (GEMM1/2/3, prior, assembly, store) tile j-1
// ---------------------------------------------------------------------------
__global__ void __launch_bounds__(256, 2)
sdf_persist(const float* __restrict__ inputs,
            const float* __restrict__ tables,
            float* __restrict__ out,
            int N, int ntiles, LevelP P) {
    extern __shared__ float smem[];
    float* sw    = smem;
    float* encT  = smem + SM_ENC;
    float* featT = smem + SM_FEAT;
    float* h1T   = smem + SM_H1;       // also out-stage
    float* sZ    = smem + SM_Z;
    float* sX64  = smem + SM_X64;
    float* sPZ   = smem + SM_PZ;

    const int tid = threadIdx.x;

    // one-time weight load
    {
        const float4* src = reinterpret_cast<const float4*>(g_w.wp1);
        float4* dst = reinterpret_cast<float4*>(sw);
        #pragma unroll
        for (int i = tid; i < TOTW / 4; i += 256) dst[i] = src[i];
    }

    int myTiles = 0;
    if ((int)blockIdx.x < ntiles)
        myTiles = (ntiles - blockIdx.x + gridDim.x - 1) / gridDim.x;

    for (int j = 0; j <= myTiles; j++) {
        __syncthreads();   // pipeline boundary (also covers the weight load at j=0)

        if (tid < 128) {
            // ========================== GATHER CREW ==========================
            if (j < myTiles) {
                const int buf  = j & 1;
                const int tile = blockIdx.x + j * gridDim.x;
                const int base = tile * 128;
                const int cnt  = min(128, N - base);
                const int p    = tid;

                float x = 0.f, y = 0.f, z = 0.f;
                if (p < cnt) {
                    const float* ip = inputs + (size_t)(base + p) * 3;
                    x = ip[0]; y = ip[1]; z = ip[2];
                }
                sZ[buf * 128 + p] = z;

                // frequency encoding
                {
                    const float PIF = 3.14159265358979323846f;
                    float s, c, e[12];
                    sincosf(x * PIF,          &s, &c); e[0] = s; e[3]  = c;
                    sincosf(x * (2.0f * PIF), &s, &c); e[1] = s; e[4]  = c;
                    sincosf(x * (4.0f * PIF), &s, &c); e[2] = s; e[5]  = c;
                    sincosf(y * PIF,          &s, &c); e[6] = s; e[9]  = c;
                    sincosf(y * (2.0f * PIF), &s, &c); e[7] = s; e[10] = c;
                    sincosf(y * (4.0f * PIF), &s, &c); e[8] = s; e[11] = c;
                    float* eb = encT + buf * 1536;
                    #pragma unroll
                    for (int i = 0; i < 12; i++) eb[i * 128 + p] = (p < cnt) ? e[i] : 0.0f;
                }

                // hash-grid gather
                float feat[32];
                if (p < cnt) {
                    const float u = __fadd_rn(__fdiv_rn(x, 30.0f), 0.5f);
                    const float v = __fadd_rn(__fdiv_rn(y, 30.0f), 0.5f);
                    const float2* tb = reinterpret_cast<const float2*>(tables);
                    #pragma unroll
                    for (int l = 0; l < NLEV; l++) {
                        float s  = P.scale[l];
                        float px = __fadd_rn(__fmul_rn(u, s), 0.5f);
                        float py = __fadd_rn(__fmul_rn(v, s), 0.5f);
                        float fx = floorf(px), fy = floorf(py);
                        float wx = px - fx,    wy = py - fy;
                        int ix = (int)fx, iy = (int)fy;
                        int i00, i10, i01, i11;
                        if (P.dense[l]) {
                            int r = P.res[l];
                            i00 = ix + iy * r;  i10 = i00 + 1;
                            i01 = i00 + r;      i11 = i01 + 1;
                            i00 = min(max(i00, 0), TSZ - 1);
                            i10 = min(max(i10, 0), TSZ - 1);
                            i01 = min(max(i01, 0), TSZ - 1);
                            i11 = min(max(i11, 0), TSZ - 1);
                        } else {
                            unsigned ux = (unsigned)ix, uy = (unsigned)iy;
                            unsigned hy0 = uy * HASH_PRIME;
                            unsigned hy1 = (uy + 1u) * HASH_PRIME;
                            i00 = (int)((ux        ^ hy0) & TMASK);
                            i10 = (int)(((ux + 1u) ^ hy0) & TMASK);
                            i01 = (int)((ux        ^ hy1) & TMASK);
                            i11 = (int)(((ux + 1u) ^ hy1) & TMASK);
                        }
                        const float2* t = tb + (size_t)l * TSZ;
                        float2 f00 = __ldg(t + i00);
                        float2 f10 = __ldg(t + i10);
                        float2 f01 = __ldg(t + i01);
                        float2 f11 = __ldg(t + i11);
                        float omx = 1.0f - wx, omy = 1.0f - wy;
                        feat[2 * l]     = (f00.x * omx + f10.x * wx) * omy + (f01.x * omx + f11.x * wx) * wy;
                        feat[2 * l + 1] = (f00.y * omx + f10.y * wx) * omy + (f01.y * omx + f11.y * wx) * wy;
                    }
                } else {
                    #pragma unroll
                    for (int k = 0; k < 32; k++) feat[k] = 0.0f;
                }
                float* fb = featT + buf * 4096;
                float x64 = 0.0f;
                #pragma unroll
                for (int k = 0; k < 32; k++) {
                    fb[k * 128 + p] = feat[k];
                    x64 += feat[k] * sw[OFF_WT + k * 68 + 64];
                }
                sX64[buf * 128 + p] = x64 + sw[OFF_BT + 64];
            }
        } else {
            // ============================ MLP CREW ===========================
            if (j >= 1) {
                const int buf  = (j - 1) & 1;
                const int tile = blockIdx.x + (j - 1) * gridDim.x;
                const int base = tile * 128;
                const int cnt  = min(128, N - base);
                const int m  = tid - 128;
                const int pg = m >> 3;        // 16 groups of 8 points
                const int cg = m & 7;         // 8 groups: cols {cg*4..+4} u {32+cg*4..+4}

                u64 acc[32];

                // --- GEMM1: enc @ Wp1 ---
                #pragma unroll
                for (int q = 0; q < 32; q++) acc[q] = 0ull;
                gemm88<12, 64, 0, 12>(acc, encT + buf * 1536, sw + OFF_WP1, pg, cg);
                bar_mlp();
                // sigmoid + swizzled transposed store to h1T
                #pragma unroll
                for (int c = 0; c < 8; c++) {
                    int r = (c & 3) + cg * 4 + ((c >> 2) << 5);
                    float* rw = h1T + r * 128 + ((pg ^ ((r >> 2) & 3)) << 3);
                    #pragma unroll
                    for (int q = 0; q < 4; q++) {
                        int p2 = (q + pg) & 3;
                        float a, b; unpack2(acc[p2 * 8 + c], a, b);
                        *reinterpret_cast<u64*>(rw + 2 * p2) = pack2(sigm(a), sigm(b));
                    }
                }
                bar_mlp();

                // --- GEMM2: h1 @ Wp2 (swizzled A) ---
                #pragma unroll
                for (int q = 0; q < 32; q++) acc[q] = 0ull;
                gemm88<64, 64, 1, 8>(acc, h1T, sw + OFF_WP2, pg, cg);
                // prior partials (kept in regs through GEMM3)
                float ppa[4], ppb[4];
                #pragma unroll
                for (int p2 = 0; p2 < 4; p2++) { ppa[p2] = 0.f; ppb[p2] = 0.f; }
                #pragma unroll
                for (int c = 0; c < 8; c++) {
                    int col = (c & 3) + cg * 4 + ((c >> 2) << 5);
                    float w3 = sw[OFF_WP3 + col];
                    #pragma unroll
                    for (int p2 = 0; p2 < 4; p2++) {
                        float a, b; unpack2(acc[p2 * 8 + c], a, b);
                        ppa[p2] += sigm(a) * w3;
                        ppb[p2] += sigm(b) * w3;
                    }
                }

                // --- GEMM3: feat @ wt[:,0:64] ---
                #pragma unroll
                for (int q = 0; q < 32; q++) acc[q] = 0ull;
                gemm88<32, 68, 0, 8>(acc, featT + buf * 4096, sw + OFF_WT, pg, cg);
                bar_mlp();   // all featT reads done -> safe to reuse as sPar

                // partial-prior store (featT[buf] reuse, stride 136, rotated p2)
                float* sPar = featT + buf * 4096;
                #pragma unroll
                for (int q = 0; q < 4; q++) {
                    int p2 = (q + pg) & 3;
                    *reinterpret_cast<u64*>(sPar + cg * 136 + pg * 8 + 2 * p2) =
                        pack2(ppa[p2], ppb[p2]);
                }
                bar_mlp();

                // prior reduction -> sPZ
                {
                    float pr = 0.0f;
                    #pragma unroll
                    for (int c = 0; c < 8; c++) pr += sPar[c * 136 + m];
                    sPZ[m] = (sZ[buf * 128 + m] - sw[OFF_BT]) - pr;
                }
                bar_mlp();

                // assembly into out-stage (h1T region), rotated p2 for banks
                float* ost = h1T;
                #pragma unroll
                for (int c = 0; c < 8; c++) {
                    int col = (c & 3) + cg * 4 + ((c >> 2) << 5);
                    float bias = sw[OFF_BT + col];
                    #pragma unroll
                    for (int q = 0; q < 4; q++) {
                        int p2 = (q + cg) & 3;
                        float a, b; unpack2(acc[p2 * 8 + c], a, b);
                        int pt = pg * 8 + 2 * p2;
                        if (col == 0) {
                            ost[pt * 65]       = sPZ[pt] - a;
                            ost[(pt + 1) * 65] = sPZ[pt + 1] - b;
                        } else {
                            ost[pt * 65 + col]       = a + bias;
                            ost[(pt + 1) * 65 + col] = b + bias;
                        }
                    }
                }
                ost[m * 65 + 64] = sX64[buf * 128 + m];
                bar_mlp();

                // coalesced flush
                if (cnt == 128) {
                    float4* o4 = reinterpret_cast<float4*>(out + (size_t)base * 65);
                    const float4* s4 = reinterpret_cast<const float4*>(ost);
                    #pragma unroll 4
                    for (int t = m; t < (128 * 65) / 4; t += 128) o4[t] = s4[t];
                } else if (cnt > 0) {
                    const int tot = cnt * 65;
                    for (int t = m; t < tot; t += 128)
                        out[(size_t)base * 65 + t] = ost[t];
                }
            }
        }
    }
}

// ---------------------------------------------------------------------------
// Launch
// ---------------------------------------------------------------------------
extern "C" void kernel_launch(void* const* d_in, const int* in_sizes, int n_in,
                              void* d_out, int out_size) {
    const float* inputs  = (const float*)d_in[0];
    const float* tables  = (const float*)d_in[1];
    const float* W_tiny  = (const float*)d_in[2];
    const float* b_tiny  = (const float*)d_in[3];
    const float* Wp1     = (const float*)d_in[4];
    const float* Wp2     = (const float*)d_in[5];
    const float* Wp3     = (const float*)d_in[6];
    float* out           = (float*)d_out;

    const int N = in_sizes[0] / 3;
    const int ntiles = (N + 127) / 128;

    LevelP P;
    for (int l = 0; l < NLEV; l++) {
        double sc = pow(2.0, (double)l * log2(1.5)) * 16.0 - 1.0;
        int res = (int)ceil(sc) + 1;
        P.scale[l] = (float)sc;
        P.res[l]   = res;
        P.dense[l] = ((long long)res * (long long)res <= (long long)TSZ) ? 1 : 0;
    }

    static int nblocks = 0;
    if (!nblocks) {
        int dev = 0, sms = 148;
        cudaGetDevice(&dev);
        cudaDeviceGetAttribute(&sms, cudaDevAttrMultiProcessorCount, dev);
        nblocks = 2 * sms;
        cudaFuncSetAttribute(sdf_persist,
                             cudaFuncAttributeMaxDynamicSharedMemorySize, SMEM_BYTES);
    }

    prep_weights<<<1, 256>>>(W_tiny, b_tiny, Wp1, Wp2, Wp3);
    sdf_persist<<<nblocks, 256, SMEM_BYTES>>>(inputs, tables, out, N, ntiles, P);
}

// round 7
// speedup vs baseline: 1.4084x; 1.4084x over previous
#include <cuda_runtime.h>
#include <cuda_bf16.h>
#include <math.h>

// ---------------------------------------------------------------------------
// Problem constants
// ---------------------------------------------------------------------------
#define NLEV 16
#define TSZ  (1 << 19)
#define TMASK (TSZ - 1)
#define HASH_PRIME 2654435761u

typedef unsigned long long u64;

// Weight blob: wp1[12*64] | wp2[64*64] | wp3[64] | wt[32*68] | bt[68]
#define OFF_WP1 0
#define OFF_WP2 768
#define OFF_WP3 4864
#define OFF_WT  4928
#define OFF_BT  7104
#define TOTW    7172

struct __align__(16) Weights {
    float wp1[12 * 64];
    float wp2[64 * 64];
    float wp3[64];
    float wt [32 * 68];
    float bt [68];
};
__device__ Weights g_w;

struct LevelP {
    float scale[NLEV];
    int   res[NLEV];
    int   dense[NLEV];
};

// Shared layout (floats); every region 16B aligned
#define SM_ENC   TOTW               // 13 x 128 = 1664 (row 12 = prefetch slack)
#define SM_FEAT  (SM_ENC + 1664)    // 33 x 128 = 4224 (row 32 = slack; sPar reuse)
#define SM_H1    (SM_FEAT + 4224)   // 65 x 128 = 8320 (row 64 = slack; out-stage 128x65)
#define SM_Z     (SM_H1 + 8320)     // 128
#define SM_X64   (SM_Z + 128)       // 256 (two halves)
#define SM_PZ    (SM_X64 + 256)     // 128
#define SMEM_FLOATS (SM_PZ + 128)
#define SMEM_BYTES  (SMEM_FLOATS * 4)

// ---------------------------------------------------------------------------
// f32x2 helpers
// ---------------------------------------------------------------------------
__device__ __forceinline__ u64 dup2(float a) {
    u64 r; asm("mov.b64 %0, {%1, %1};" : "=l"(r) : "f"(a)); return r;
}
__device__ __forceinline__ u64 pack2(float a, float b) {
    u64 r; asm("mov.b64 %0, {%1, %2};" : "=l"(r) : "f"(a), "f"(b)); return r;
}
__device__ __forceinline__ void unpack2(u64 v, float &a, float &b) {
    asm("mov.b64 {%0, %1}, %2;" : "=f"(a), "=f"(b) : "l"(v));
}
__device__ __forceinline__ void fma2(u64 &d, u64 a, u64 b) {
    asm("fma.rn.f32x2 %0, %1, %2, %0;" : "+l"(d) : "l"(a), "l"(b));
}
__device__ __forceinline__ float sigm(float x) {
    return __fdividef(1.0f, 1.0f + __expf(-x));
}

// ---------------------------------------------------------------------------
// 8pt x 4col register-tiled GEMM, warp covers 32pts x 32cols:
//   pg = (w>>1)*4 + (lane>>3)   (4 distinct pg/warp -> A: 1 wf per LDS.128)
//   cg = (w&1)*8 + (lane&7)     (8 distinct cg/warp -> B: 1 wf)
// acc[p2*4+c] packs points (pg*8+2p2, +1) for col cg*4+c.
// SWZ: A row k stored with point-block swizzle pg ^ ((k>>2)&3).
// A prefetch reads one row past K (slack row, value discarded).
// ---------------------------------------------------------------------------
template <int K, int NC, int SWZ, int UNR>
__device__ __forceinline__ void gemm84(u64* __restrict__ acc,
                                       const float* __restrict__ aT,
                                       const float* __restrict__ B,
                                       int pg, int cg) {
    const float* bp = B + cg * 4;
    #define A_PTR(kk) (aT + (kk) * 128 + ((SWZ ? (pg ^ (((kk) >> 2) & 3)) : pg) << 3))
    const float* a0 = A_PTR(0);
    ulonglong2 A0 = *reinterpret_cast<const ulonglong2*>(a0);
    ulonglong2 A1 = *reinterpret_cast<const ulonglong2*>(a0 + 4);
    #pragma unroll UNR
    for (int k = 0; k < K; k++) {
        const float* an = A_PTR(k + 1);
        ulonglong2 nA0 = *reinterpret_cast<const ulonglong2*>(an);
        ulonglong2 nA1 = *reinterpret_cast<const ulonglong2*>(an + 4);
        float4 b4 = *reinterpret_cast<const float4*>(bp + k * NC);
        u64 b0 = dup2(b4.x), b1 = dup2(b4.y), b2 = dup2(b4.z), b3 = dup2(b4.w);
        u64 a[4] = {A0.x, A0.y, A1.x, A1.y};
        #pragma unroll
        for (int p = 0; p < 4; p++) {
            fma2(acc[p * 4 + 0], a[p], b0);
            fma2(acc[p * 4 + 1], a[p], b1);
            fma2(acc[p * 4 + 2], a[p], b2);
            fma2(acc[p * 4 + 3], a[p], b3);
        }
        A0 = nA0; A1 = nA1;
    }
    #undef A_PTR
}

// ---------------------------------------------------------------------------
// Prep kernel
// ---------------------------------------------------------------------------
__global__ void prep_weights(const float* __restrict__ W_tiny,
                             const float* __restrict__ b_tiny,
                             const float* __restrict__ Wp1,
                             const float* __restrict__ Wp2,
                             const float* __restrict__ Wp3) {
    int t = threadIdx.x;
    for (int i = t; i < 12 * 64; i += blockDim.x) g_w.wp1[i] = Wp1[i];
    for (int i = t; i < 64 * 64; i += blockDim.x) g_w.wp2[i] = Wp2[i];
    if (t < 64) g_w.wp3[t] = Wp3[t];
    for (int i = t; i < 32 * 68; i += blockDim.x) {
        int k = i / 68, j = i % 68;
        g_w.wt[i] = (j < 65) ? W_tiny[k * 65 + j] : 0.0f;
    }
    if (t < 68) g_w.bt[t] = (t < 65) ? b_tiny[t] : 0.0f;
}

// ---------------------------------------------------------------------------
// One level of hash-grid bilinear lookup
// ---------------------------------------------------------------------------
__device__ __forceinline__ void hash_level(const float2* __restrict__ tb,
                                           float u, float v,
                                           float scale, int res, int dense,
                                           float &f0, float &f1) {
    float px = __fadd_rn(__fmul_rn(u, scale), 0.5f);
    float py = __fadd_rn(__fmul_rn(v, scale), 0.5f);
    float fx = floorf(px), fy = floorf(py);
    float wx = px - fx,    wy = py - fy;
    int ix = (int)fx, iy = (int)fy;
    int i00, i10, i01, i11;
    if (dense) {
        int r = res;
        i00 = ix + iy * r;  i10 = i00 + 1;
        i01 = i00 + r;      i11 = i01 + 1;
        i00 = min(max(i00, 0), TSZ - 1);
        i10 = min(max(i10, 0), TSZ - 1);
        i01 = min(max(i01, 0), TSZ - 1);
        i11 = min(max(i11, 0), TSZ - 1);
    } else {
        unsigned ux = (unsigned)ix, uy = (unsigned)iy;
        unsigned hy0 = uy * HASH_PRIME;
        unsigned hy1 = (uy + 1u) * HASH_PRIME;
        i00 = (int)((ux        ^ hy0) & TMASK);
        i10 = (int)(((ux + 1u) ^ hy0) & TMASK);
        i01 = (int)((ux        ^ hy1) & TMASK);
        i11 = (int)(((ux + 1u) ^ hy1) & TMASK);
    }
    float2 f00 = __ldg(tb + i00);
    float2 f10 = __ldg(tb + i10);
    float2 f01 = __ldg(tb + i01);
    float2 f11 = __ldg(tb + i11);
    float omx = 1.0f - wx, omy = 1.0f - wy;
    f0 = (f00.x * omx + f10.x * wx) * omy + (f01.x * omx + f11.x * wx) * wy;
    f1 = (f00.y * omx + f10.y * wx) * omy + (f01.y * omx + f11.y * wx) * wy;
}

// ---------------------------------------------------------------------------
// Fused kernel: 128-pt tile, 256 threads; 2 threads/pt in gather phase
// ---------------------------------------------------------------------------
__global__ void __launch_bounds__(256, 2)
sdf_kernel(const float* __restrict__ inputs,
           const float* __restrict__ tables,
           float* __restrict__ out,
           int N, LevelP P) {
    extern __shared__ float smem[];
    float* sw    = smem;
    float* encT  = smem + SM_ENC;
    float* featT = smem + SM_FEAT;
    float* h1T   = smem + SM_H1;     // also out-stage
    float* sZ    = smem + SM_Z;
    float* sX64  = smem + SM_X64;
    float* sPZ   = smem + SM_PZ;

    const int tid  = threadIdx.x;
    const int lane = tid & 31;
    const int w    = tid >> 5;
    const int pg   = ((w >> 1) << 2) + (lane >> 3);   // 0..15
    const int cg   = ((w & 1) << 3) + (lane & 7);     // 0..15
    const int cgl  = lane & 7;
    const int base = blockIdx.x * 128;
    const int cnt  = min(128, N - base);

    // ---- cooperative weight load ----
    {
        const float4* src = reinterpret_cast<const float4*>(g_w.wp1);
        float4* dst = reinterpret_cast<float4*>(sw);
        #pragma unroll
        for (int i = tid; i < TOTW / 4; i += 256) dst[i] = src[i];
    }
    __syncthreads();   // weights visible (x64 dot below reads sw)

    // =======================================================================
    // Gather phase: 2 threads per point.  half 0 -> even levels + x-sincos,
    //               half 1 -> odd levels + y-sincos.
    // =======================================================================
    {
        const int half = tid >> 7;          // 0 or 1
        const int p    = tid & 127;
        float x = 0.f, y = 0.f;
        if (p < cnt) {
            const float* ip = inputs + (size_t)(base + p) * 3;
            x = ip[0]; y = ip[1];
            if (half == 0) sZ[p] = ip[2];
        } else if (half == 0) sZ[p] = 0.f;

        // sincos: half 0 encodes x (rows 0-2 sin, 3-5 cos), half 1 y (rows 6-11)
        {
            const float PIF = 3.14159265358979323846f;
            const float cc = (half == 0) ? x : y;
            float s0, c0, s1, c1, s2, c2;
            sincosf(cc * PIF,          &s0, &c0);
            sincosf(cc * (2.0f * PIF), &s1, &c1);
            sincosf(cc * (4.0f * PIF), &s2, &c2);
            float* eb = encT + half * 6 * 128 + p;
            if (p < cnt) {
                eb[0 * 128] = s0; eb[1 * 128] = s1; eb[2 * 128] = s2;
                eb[3 * 128] = c0; eb[4 * 128] = c1; eb[5 * 128] = c2;
            } else {
                eb[0 * 128] = 0.f; eb[1 * 128] = 0.f; eb[2 * 128] = 0.f;
                eb[3 * 128] = 0.f; eb[4 * 128] = 0.f; eb[5 * 128] = 0.f;
            }
        }

        // hash levels (8 per thread, parity split)
        float x64 = 0.0f;
        const float u = __fadd_rn(__fdiv_rn(x, 30.0f), 0.5f);
        const float v = __fadd_rn(__fdiv_rn(y, 30.0f), 0.5f);
        const float2* tb = reinterpret_cast<const float2*>(tables);
        if (p < cnt) {
            #pragma unroll
            for (int i = 0; i < 8; i++) {
                const int l = 2 * i + half;
                float f0, f1;
                hash_level(tb + (size_t)l * TSZ, u, v,
                           P.scale[l], P.res[l], P.dense[l], f0, f1);
                featT[(2 * l) * 128 + p]     = f0;
                featT[(2 * l + 1) * 128 + p] = f1;
                x64 += f0 * sw[OFF_WT + (2 * l) * 68 + 64];
                x64 += f1 * sw[OFF_WT + (2 * l + 1) * 68 + 64];
            }
        } else {
            #pragma unroll
            for (int i = 0; i < 8; i++) {
                const int l = 2 * i + half;
                featT[(2 * l) * 128 + p]     = 0.f;
                featT[(2 * l + 1) * 128 + p] = 0.f;
            }
        }
        sX64[half * 128 + p] = x64;
    }
    __syncthreads();

    u64 acc[16];

    // ---- GEMM1: h1 = sigmoid(enc @ Wp1) ----
    #pragma unroll
    for (int q = 0; q < 16; q++) acc[q] = 0ull;
    gemm84<12, 64, 0, 12>(acc, encT, sw + OFF_WP1, pg, cg);
    // swizzled + rotated transposed store to h1T (no sync needed: disjoint region)
    #pragma unroll
    for (int c = 0; c < 4; c++) {
        const int col = cg * 4 + c;
        float* rw = h1T + col * 128 + ((pg ^ ((col >> 2) & 3)) << 3);
        #pragma unroll
        for (int q = 0; q < 4; q++) {
            const int p2 = (q + cgl) & 3;
            float a, b; unpack2(acc[p2 * 4 + c], a, b);
            *reinterpret_cast<u64*>(rw + 2 * p2) = pack2(sigm(a), sigm(b));
        }
    }
    __syncthreads();

    // ---- GEMM2: h2 = sigmoid(h1 @ Wp2); prior partials ----
    #pragma unroll
    for (int q = 0; q < 16; q++) acc[q] = 0ull;
    gemm84<64, 64, 1, 8>(acc, h1T, sw + OFF_WP2, pg, cg);
    float ppa[4], ppb[4];
    #pragma unroll
    for (int p2 = 0; p2 < 4; p2++) { ppa[p2] = 0.f; ppb[p2] = 0.f; }
    #pragma unroll
    for (int c = 0; c < 4; c++) {
        const float w3 = sw[OFF_WP3 + cg * 4 + c];
        #pragma unroll
        for (int p2 = 0; p2 < 4; p2++) {
            float a, b; unpack2(acc[p2 * 4 + c], a, b);
            ppa[p2] += sigm(a) * w3;
            ppb[p2] += sigm(b) * w3;
        }
    }

    // ---- GEMM3: feat @ wt[:,0:64] ----
    #pragma unroll
    for (int q = 0; q < 16; q++) acc[q] = 0ull;
    gemm84<32, 68, 0, 8>(acc, featT, sw + OFF_WT, pg, cg);
    __syncthreads();   // featT reads done -> reuse as sPar

    // prior partial store (stride 136, rotated p2)
    {
        float* sPar = featT;
        #pragma unroll
        for (int q = 0; q < 4; q++) {
            const int p2 = (q + cgl) & 3;
            *reinterpret_cast<u64*>(sPar + cg * 136 + pg * 8 + 2 * p2) =
                pack2(ppa[p2], ppb[p2]);
        }
    }
    __syncthreads();

    // prior reduction + x64 combine (threads 0-127)
    if (tid < 128) {
        const float* sPar = featT;
        float pr = 0.0f;
        #pragma unroll
        for (int c = 0; c < 16; c++) pr += sPar[c * 136 + tid];
        sPZ[tid] = (sZ[tid] - sw[OFF_BT]) - pr;          // z - bt0 - prior
        sX64[tid] = sX64[tid] + sX64[128 + tid] + sw[OFF_BT + 64];
    }
    __syncthreads();

    // ---- assembly into out-stage (h1T region) ----
    {
        float* ost = h1T;
        #pragma unroll
        for (int c = 0; c < 4; c++) {
            const int col = cg * 4 + c;
            const float bias = sw[OFF_BT + col];
            #pragma unroll
            for (int q = 0; q < 4; q++) {
                const int p2 = (q + cgl) & 3;
                float a, b; unpack2(acc[p2 * 4 + c], a, b);
                const int pt = pg * 8 + 2 * p2;
                if (col == 0) {
                    ost[pt * 65]       = sPZ[pt] - a;
                    ost[(pt + 1) * 65] = sPZ[pt + 1] - b;
                } else {
                    ost[pt * 65 + col]       = a + bias;
                    ost[(pt + 1) * 65 + col] = b + bias;
                }
            }
        }
        if (tid < 128) ost[tid * 65 + 64] = sX64[tid];
    }
    __syncthreads();

    // ---- coalesced flush ----
    if (cnt == 128) {
        float4* o4 = reinterpret_cast<float4*>(out + (size_t)base * 65);
        const float4* s4 = reinterpret_cast<const float4*>(h1T);
        #pragma unroll
        for (int t = tid; t < (128 * 65) / 4; t += 256) o4[t] = s4[t];
    } else if (cnt > 0) {
        const int tot = cnt * 65;
        for (int t = tid; t < tot; t += 256) out[(size_t)base * 65 + t] = h1T[t];
    }
}

// ---------------------------------------------------------------------------
// Launch
// ---------------------------------------------------------------------------
extern "C" void kernel_launch(void* const* d_in, const int* in_sizes, int n_in,
                              void* d_out, int out_size) {
    const float* inputs  = (const float*)d_in[0];
    const float* tables  = (const float*)d_in[1];
    const float* W_tiny  = (const float*)d_in[2];
    const float* b_tiny  = (const float*)d_in[3];
    const float* Wp1     = (const float*)d_in[4];
    const float* Wp2     = (const float*)d_in[5];
    const float* Wp3     = (const float*)d_in[6];
    float* out           = (float*)d_out;

    const int N = in_sizes[0] / 3;

    LevelP P;
    for (int l = 0; l < NLEV; l++) {
        double sc = pow(2.0, (double)l * log2(1.5)) * 16.0 - 1.0;
        int res = (int)ceil(sc) + 1;
        P.scale[l] = (float)sc;
        P.res[l]   = res;
        P.dense[l] = ((long long)res * (long long)res <= (long long)TSZ) ? 1 : 0;
    }

    static int attr_done = 0;
    if (!attr_done) {
        cudaFuncSetAttribute(sdf_kernel,
                             cudaFuncAttributeMaxDynamicSharedMemorySize, SMEM_BYTES);
        attr_done = 1;
    }

    prep_weights<<<1, 256>>>(W_tiny, b_tiny, Wp1, Wp2, Wp3);

    const int tiles = (N + 127) / 128;
    sdf_kernel<<<tiles, 256, SMEM_BYTES>>>(inputs, tables, out, N, P);
}